// round 12
// baseline (speedup 1.0000x reference)
#include <cuda_runtime.h>
#include <cstdint>

// Conv2d N=32, CIN=3, H=W=224, COUT=64, 3x3, s1, p1, fp32.
// Implicit GEMM via mma.sync.m16n8k16 bf16->f32, 3-pass hi/lo fp32 emulation.
// R12: 32-px row-aligned warp tiles (2 MMA pixel-sets), sliding-window shuffle
// distribution (6-wide S per (ci,ky) shared by all kx and 4 px), and STG.128
// stores hitting the 128B-per-wavefront minimum. acc processed in nt-halves
// to hold registers ~168 (3 blocks/SM).

#define HWDIM 224
#define IMG (HWDIM*HWDIM)        // 50176
#define COUT 64
#define CIN 3
#define NTHREADS 128
#define FULL 0xffffffffu

__device__ __forceinline__ uint32_t cvt_bf16x2(float hi, float lo) {
    uint32_t d;
    asm("cvt.rn.bf16x2.f32 %0, %1, %2;" : "=r"(d) : "f"(hi), "f"(lo));
    return d;
}
__device__ __forceinline__ void mma_bf16(float* d, const uint32_t* a, const uint32_t* b) {
    asm volatile(
        "mma.sync.aligned.m16n8k16.row.col.f32.bf16.bf16.f32 "
        "{%0,%1,%2,%3}, {%4,%5,%6,%7}, {%8,%9}, {%0,%1,%2,%3};"
        : "+f"(d[0]), "+f"(d[1]), "+f"(d[2]), "+f"(d[3])
        : "r"(a[0]), "r"(a[1]), "r"(a[2]), "r"(a[3]), "r"(b[0]), "r"(b[1]));
}

__global__ __launch_bounds__(NTHREADS, 3)
void conv_mma(const float* __restrict__ xin, const float* __restrict__ wgt,
              const float* __restrict__ bias, float* __restrict__ out)
{
    const int tid  = threadIdx.x;
    const int warp = tid >> 5;
    const int lane = tid & 31;
    const int lg   = lane >> 2;     // quad index 0..7 (px base 4*lg)
    const int cc   = (lane & 3) * 2;

    // grid: 32 imgs x 7 rowgroups(32 rows) x 7 x-segments(32 px)
    const int b   = blockIdx.x;
    const int n   = b / 49;
    const int rem = b % 49;
    const int rg  = rem / 7;
    const int xc  = rem % 7;
    const float* in_n  = xin + (size_t)n * (CIN * IMG);
    float*       out_n = out + (size_t)n * (COUT * IMG);
    const int x0    = xc * 32;
    const int ybase = rg * 32 + warp * 8;

    // ---- B (weight+bias) fragments, hi/lo, built once per thread ----
    uint32_t BH[8][2][2], BL[8][2][2];
#pragma unroll
    for (int nt = 0; nt < 8; ++nt) {
        const int co = nt * 8 + lg;
#pragma unroll
        for (int s = 0; s < 2; ++s)
#pragma unroll
        for (int r = 0; r < 2; ++r) {
            const int k0 = 16 * s + cc + 8 * r;
            const int k1 = k0 + 1;
            const float f0 = (k0 < 27) ? wgt[co * 27 + k0] : (k0 == 27 ? bias[co] : 0.f);
            const float f1 = (k1 < 27) ? wgt[co * 27 + k1] : (k1 == 27 ? bias[co] : 0.f);
            const uint32_t h = cvt_bf16x2(f1, f0);
            const float l0 = f0 - __uint_as_float(h << 16);
            const float l1 = f1 - __uint_as_float(h & 0xffff0000u);
            BH[nt][s][r] = h;
            BL[nt][s][r] = cvt_bf16x2(l1, l0);
        }
    }

    // ---- patch layout: lane u -> x = x0-1+u (u=0..31); EP lanes 0,1 -> x0+31+lane ----
    const bool pa_ok = !(xc == 0 && lane == 0);                  // x = -1
    const bool ep_ok = (lane < 2) && !(xc == 6 && lane == 1);    // x = 224
    const float* pa_ptr = in_n + x0 - 1 + lane;
    const float* ep_ptr = in_n + x0 + 31 + lane;

    float PA[CIN][3], EP[CIN][3];
#pragma unroll
    for (int j = 0; j < 3; ++j) {
        const int yy  = ybase - 1 + j;
        const bool rok = ((unsigned)yy < (unsigned)HWDIM);
#pragma unroll
        for (int ci = 0; ci < CIN; ++ci) {
            PA[ci][j] = (pa_ok && rok) ? __ldg(pa_ptr + ci * IMG + yy * HWDIM) : 0.f;
            EP[ci][j] = (ep_ok && rok) ? __ldg(ep_ptr + ci * IMG + yy * HWDIM) : 0.f;
        }
    }

    for (int it = 0; it < 8; ++it) {
        const int y = ybase + it;

        // ---- distribute: sliding windows S[0..5] per (ci,ky), select taps ----
        // v[t][j] = input for tap t (k = cc + offs[t]) at pixel 4lg+j.
        float v[8][4];
#pragma unroll
        for (int t = 0; t < 8; ++t) {
            const float d = (t == 7 && cc == 2) ? 1.f : 0.f;  // k=27 bias tap
            v[t][0] = d; v[t][1] = d; v[t][2] = d; v[t][3] = d;
        }
#pragma unroll
        for (int ci = 0; ci < CIN; ++ci)
#pragma unroll
        for (int ky = 0; ky < 3; ++ky) {
            float S[6];
#pragma unroll
            for (int w = 0; w < 4; ++w)
                S[w] = __shfl_sync(FULL, PA[ci][ky], 4 * lg + w);
#pragma unroll
            for (int w = 4; w < 6; ++w) {
                const float sa = __shfl_sync(FULL, PA[ci][ky], (4 * lg + w) & 31);
                const float se = __shfl_sync(FULL, EP[ci][ky], (4 * lg + w - 32) & 31);
                S[w] = (lg == 7) ? se : sa;   // u >= 32 only when lg == 7
            }
#pragma unroll
            for (int kx = 0; kx < 3; ++kx) {
                const int k  = ci * 9 + ky * 3 + kx;
                const int ck = k & 6;
                const int t  = 2 * (k >> 3) + (k & 1);
                if (cc == ck) {
                    v[t][0] = S[kx];     v[t][1] = S[kx + 1];
                    v[t][2] = S[kx + 2]; v[t][3] = S[kx + 3];
                }
            }
        }

        // ---- split hi/lo, pack A fragments for both pixel sets ----
        uint32_t AH0[2][4], AL0[2][4], AH1[2][4], AL1[2][4];
#pragma unroll
        for (int s = 0; s < 2; ++s)
#pragma unroll
        for (int r = 0; r < 2; ++r) {
            const int t0 = 4 * s + 2 * r;
#pragma unroll
            for (int set = 0; set < 2; ++set) {
                const int j0 = 2 * set;          // px offsets j0, j0+1
                const float f00 = v[t0][j0],     f01 = v[t0 + 1][j0];
                const float f10 = v[t0][j0 + 1], f11 = v[t0 + 1][j0 + 1];
                const uint32_t h0 = cvt_bf16x2(f01, f00);
                const uint32_t h1 = cvt_bf16x2(f11, f10);
                const float l00 = f00 - __uint_as_float(h0 << 16);
                const float l01 = f01 - __uint_as_float(h0 & 0xffff0000u);
                const float l10 = f10 - __uint_as_float(h1 << 16);
                const float l11 = f11 - __uint_as_float(h1 & 0xffff0000u);
                uint32_t* AH = set ? &AH1[s][0] : &AH0[s][0];
                uint32_t* AL = set ? &AL1[s][0] : &AL0[s][0];
                AH[2 * r]     = h0;
                AH[2 * r + 1] = h1;
                AL[2 * r]     = cvt_bf16x2(l01, l00);
                AL[2 * r + 1] = cvt_bf16x2(l11, l10);
            }
        }

        // ---- prefetch next patch row (y+2), overlaps with MMAs ----
        float TPA[CIN], TEP[CIN];
        {
            const int yy  = y + 2;
            const bool rok = ((unsigned)yy < (unsigned)HWDIM);
#pragma unroll
            for (int ci = 0; ci < CIN; ++ci) {
                TPA[ci] = (pa_ok && rok) ? __ldg(pa_ptr + ci * IMG + yy * HWDIM) : 0.f;
                TEP[ci] = (ep_ok && rok) ? __ldg(ep_ptr + ci * IMG + yy * HWDIM) : 0.f;
            }
        }

        // ---- MMAs + stores in nt-halves (acc stays at 32 regs) ----
        const int p = y * HWDIM + x0 + 4 * lg;   // 16B aligned
#pragma unroll
        for (int h = 0; h < 2; ++h) {
            float acc[4][2][4];
#pragma unroll
            for (int q = 0; q < 4; ++q)
#pragma unroll
            for (int set = 0; set < 2; ++set) {
                acc[q][set][0] = 0.f; acc[q][set][1] = 0.f;
                acc[q][set][2] = 0.f; acc[q][set][3] = 0.f;
            }
#pragma unroll
            for (int q = 0; q < 4; ++q) {
                const int nt = h * 4 + q;
#pragma unroll
                for (int s = 0; s < 2; ++s) {
                    mma_bf16(acc[q][0], AH0[s], BH[nt][s]);
                    mma_bf16(acc[q][0], AH0[s], BL[nt][s]);
                    mma_bf16(acc[q][0], AL0[s], BH[nt][s]);
                    mma_bf16(acc[q][1], AH1[s], BH[nt][s]);
                    mma_bf16(acc[q][1], AH1[s], BL[nt][s]);
                    mma_bf16(acc[q][1], AL1[s], BH[nt][s]);
                }
            }
#pragma unroll
            for (int q = 0; q < 4; ++q) {
                const int co = (h * 4 + q) * 8 + cc;
                float* pl0 = out_n + (size_t)co * IMG + p;
                float4 o0, o1;
                o0.x = acc[q][0][0]; o0.y = acc[q][0][2];
                o0.z = acc[q][1][0]; o0.w = acc[q][1][2];
                o1.x = acc[q][0][1]; o1.y = acc[q][0][3];
                o1.z = acc[q][1][1]; o1.w = acc[q][1][3];
                *reinterpret_cast<float4*>(pl0)       = o0;
                *reinterpret_cast<float4*>(pl0 + IMG) = o1;
            }
        }

        // ---- rotate patch rows ----
#pragma unroll
        for (int ci = 0; ci < CIN; ++ci) {
            PA[ci][0] = PA[ci][1]; PA[ci][1] = PA[ci][2]; PA[ci][2] = TPA[ci];
            EP[ci][0] = EP[ci][1]; EP[ci][1] = EP[ci][2]; EP[ci][2] = TEP[ci];
        }
    }
}

extern "C" void kernel_launch(void* const* d_in, const int* in_sizes, int n_in,
                              void* d_out, int out_size)
{
    const float* x = (const float*)d_in[0];
    const float* w = (const float*)d_in[1];
    const float* b = (const float*)d_in[2];
    float* out = (float*)d_out;

    dim3 block(NTHREADS, 1, 1);
    dim3 grid(32 * 7 * 7, 1, 1);   // 1568 blocks
    conv_mma<<<grid, block>>>(x, w, b, out);
}

// round 13
// speedup vs baseline: 1.2997x; 1.2997x over previous
#include <cuda_runtime.h>
#include <cstdint>

// Conv2d N=32, CIN=3, H=W=224, COUT=64, 3x3, s1, p1, fp32.
// Implicit GEMM via mma.sync.m16n8k16 bf16->f32, 3-pass hi/lo fp32 emulation.
// R13 = R11 (16-px warp tiles, register patch, shuffle distribution) with the
// shuffle count halved: per (ci,ky) the 3 k-taps split into one cc-group that
// owns 2 adjacent kx (window of 3) and one that owns 1 (window of 2); three
// variable-source __shfl_syncs serve all groups at once -> 27 shfl/iter vs 54.

#define HWDIM 224
#define IMG (HWDIM*HWDIM)        // 50176
#define COUT 64
#define CIN 3
#define NTHREADS 128
#define FULL 0xffffffffu

__device__ __forceinline__ uint32_t cvt_bf16x2(float hi, float lo) {
    uint32_t d;
    asm("cvt.rn.bf16x2.f32 %0, %1, %2;" : "=r"(d) : "f"(hi), "f"(lo));
    return d;
}
__device__ __forceinline__ void mma_bf16(float* d, const uint32_t* a, const uint32_t* b) {
    asm volatile(
        "mma.sync.aligned.m16n8k16.row.col.f32.bf16.bf16.f32 "
        "{%0,%1,%2,%3}, {%4,%5,%6,%7}, {%8,%9}, {%0,%1,%2,%3};"
        : "+f"(d[0]), "+f"(d[1]), "+f"(d[2]), "+f"(d[3])
        : "r"(a[0]), "r"(a[1]), "r"(a[2]), "r"(a[3]), "r"(b[0]), "r"(b[1]));
}

__global__ __launch_bounds__(NTHREADS, 3)
void conv_mma(const float* __restrict__ xin, const float* __restrict__ wgt,
              const float* __restrict__ bias, float* __restrict__ out)
{
    const int tid  = threadIdx.x;
    const int warp = tid >> 5;
    const int lane = tid & 31;
    const int lg   = lane >> 2;     // pixel-pair index 0..7
    const int cc   = (lane & 3) * 2;

    // grid: 32 imgs x 7 rowgroups x 14 x-segments
    const int b   = blockIdx.x;
    const int n   = b / 98;
    const int rem = b % 98;
    const int rg  = rem / 14;
    const int xc  = rem % 14;
    const float* in_n  = xin + (size_t)n * (CIN * IMG);
    float*       out_n = out + (size_t)n * (COUT * IMG);
    const int x0    = xc * 16;
    const int ybase = rg * 32 + warp * 8;

    // ---- B (weight+bias) fragments, hi/lo, built once per thread ----
    uint32_t BH[8][2][2], BL[8][2][2];
#pragma unroll
    for (int nt = 0; nt < 8; ++nt) {
        const int co = nt * 8 + lg;
#pragma unroll
        for (int s = 0; s < 2; ++s)
#pragma unroll
        for (int r = 0; r < 2; ++r) {
            const int k0 = 16 * s + cc + 8 * r;
            const int k1 = k0 + 1;
            const float f0 = (k0 < 27) ? wgt[co * 27 + k0] : (k0 == 27 ? bias[co] : 0.f);
            const float f1 = (k1 < 27) ? wgt[co * 27 + k1] : (k1 == 27 ? bias[co] : 0.f);
            const uint32_t h = cvt_bf16x2(f1, f0);
            const float l0 = f0 - __uint_as_float(h << 16);
            const float l1 = f1 - __uint_as_float(h & 0xffff0000u);
            BH[nt][s][r] = h;
            BL[nt][s][r] = cvt_bf16x2(l1, l0);
        }
    }

    // ---- patch loading setup: lane u holds x = x0 - 1 + u (u = 0..17) ----
    const bool lane_ok = (lane < 18)
                      && !(xc == 0  && lane == 0)     // x = -1
                      && !(xc == 13 && lane == 17);   // x = 224
    const float* rp = in_n + x0 - 1 + lane;           // + ci*IMG + yy*HWDIM

    // ---- prologue: patch rows for iteration 0 ----
    float P[3][3];   // P[ci][j] = row (ybase - 1 + j)
#pragma unroll
    for (int j = 0; j < 3; ++j) {
        const int yy  = ybase - 1 + j;
        const bool ok = lane_ok && ((unsigned)yy < (unsigned)HWDIM);
#pragma unroll
        for (int ci = 0; ci < CIN; ++ci)
            P[ci][j] = ok ? __ldg(rp + ci * IMG + yy * HWDIM) : 0.f;
    }

    for (int it = 0; it < 8; ++it) {
        const int y = ybase + it;

        // ---- distribute patch -> taps: 3 variable-src shuffles per (ci,ky) ----
        float v0[8], v1[8];
#pragma unroll
        for (int t = 0; t < 8; ++t) {
            const float d = (t == 7 && cc == 2) ? 1.f : 0.f;  // k=27 bias tap
            v0[t] = d; v1[t] = d;
        }
#pragma unroll
        for (int ci = 0; ci < CIN; ++ci)
#pragma unroll
        for (int ky = 0; ky < 3; ++ky) {
            const int k0 = ci * 9 + ky * 3;
            // triple {k0, k0+1, k0+2}: even/odd pair shares owner (k&6).
            const int KA0  = (k0 % 2 == 0) ? k0 : k0 + 1;  // A owns KA0, KA0+1
            const int KB   = (k0 % 2 == 0) ? k0 + 2 : k0;  // B owns KB
            const int kxA0 = KA0 - k0;
            const int kxB  = KB - k0;
            const int ckA  = KA0 & 6;
            const int ckB  = KB & 6;
            const int tA0  = 2 * (KA0 >> 3) + (KA0 & 1);
            const int tA1  = 2 * ((KA0 + 1) >> 3) + ((KA0 + 1) & 1);
            const int tB   = 2 * (KB >> 3) + (KB & 1);

            const bool isA = (cc == ckA);
            const bool isB = (cc == ckB);
            const int  src = 2 * lg + (isA ? kxA0 : kxB);
            const float s0 = __shfl_sync(FULL, P[ci][ky], src);
            const float s1 = __shfl_sync(FULL, P[ci][ky], src + 1);
            const float s2 = __shfl_sync(FULL, P[ci][ky], src + 2);
            if (isA) { v0[tA0] = s0; v1[tA0] = s1; v0[tA1] = s1; v1[tA1] = s2; }
            if (isB) { v0[tB]  = s0; v1[tB]  = s1; }
        }

        // ---- split hi/lo, pack A fragments ----
        uint32_t AH[2][4], AL[2][4];
#pragma unroll
        for (int s = 0; s < 2; ++s)
#pragma unroll
        for (int r = 0; r < 2; ++r) {
            const int t0 = 4 * s + 2 * r;
            const float f00 = v0[t0], f01 = v0[t0 + 1];
            const float f10 = v1[t0], f11 = v1[t0 + 1];
            const uint32_t h0 = cvt_bf16x2(f01, f00);
            const uint32_t h1 = cvt_bf16x2(f11, f10);
            AH[s][2 * r]     = h0;
            AH[s][2 * r + 1] = h1;
            const float l00 = f00 - __uint_as_float(h0 << 16);
            const float l01 = f01 - __uint_as_float(h0 & 0xffff0000u);
            const float l10 = f10 - __uint_as_float(h1 << 16);
            const float l11 = f11 - __uint_as_float(h1 & 0xffff0000u);
            AL[s][2 * r]     = cvt_bf16x2(l01, l00);
            AL[s][2 * r + 1] = cvt_bf16x2(l11, l10);
        }

        // ---- prefetch next patch row (y+2), overlaps with MMAs ----
        float T[3];
        {
            const int yy  = y + 2;
            const bool ok = lane_ok && ((unsigned)yy < (unsigned)HWDIM);
#pragma unroll
            for (int ci = 0; ci < CIN; ++ci)
                T[ci] = ok ? __ldg(rp + ci * IMG + yy * HWDIM) : 0.f;
        }

        // ---- 48 MMAs ----
        float acc[8][4];
#pragma unroll
        for (int nt = 0; nt < 8; ++nt) {
            acc[nt][0] = 0.f; acc[nt][1] = 0.f; acc[nt][2] = 0.f; acc[nt][3] = 0.f;
        }
#pragma unroll
        for (int nt = 0; nt < 8; ++nt) {
#pragma unroll
            for (int s = 0; s < 2; ++s) {
                mma_bf16(acc[nt], AH[s], BH[nt][s]);
                mma_bf16(acc[nt], AH[s], BL[nt][s]);
                mma_bf16(acc[nt], AL[s], BH[nt][s]);
            }
        }

        // ---- store: per co, float2 of adjacent pixels (p0, p0+1) ----
        const int p0 = y * HWDIM + x0 + 2 * lg;   // even -> 8B aligned
#pragma unroll
        for (int nt = 0; nt < 8; ++nt) {
            const int co = nt * 8 + cc;
            float* pl0 = out_n + (size_t)co * IMG + p0;
            float* pl1 = pl0 + IMG;
            *reinterpret_cast<float2*>(pl0) = make_float2(acc[nt][0], acc[nt][2]);
            *reinterpret_cast<float2*>(pl1) = make_float2(acc[nt][1], acc[nt][3]);
        }

        // ---- rotate patch rows ----
#pragma unroll
        for (int ci = 0; ci < CIN; ++ci) {
            P[ci][0] = P[ci][1];
            P[ci][1] = P[ci][2];
            P[ci][2] = T[ci];
        }
    }
}

extern "C" void kernel_launch(void* const* d_in, const int* in_sizes, int n_in,
                              void* d_out, int out_size)
{
    const float* x = (const float*)d_in[0];
    const float* w = (const float*)d_in[1];
    const float* b = (const float*)d_in[2];
    float* out = (float*)d_out;

    dim3 block(NTHREADS, 1, 1);
    dim3 grid(32 * 7 * 14, 1, 1);   // 3136 blocks
    conv_mma<<<grid, block>>>(x, w, b, out);
}